// round 13
// baseline (speedup 1.0000x reference)
#include <cuda_runtime.h>
#include <cuda_bf16.h>
#include <cstdint>
#include <cstddef>

// Problem constants
#define HWC   65536          // H*W = 256*256
#define CCH   256            // channels
#define NBAT  4
#define NHEAD 8
#define HD    32
#define NGRP  32
#define CPG   8              // channels per group

// ===========================================================================
// Helpers
// ===========================================================================
__device__ __forceinline__ uint32_t smem_u32(const void* p) {
    uint32_t a;
    asm("{ .reg .u64 t; cvta.to.shared.u64 t, %1; cvt.u32.u64 %0, t; }"
        : "=r"(a) : "l"(p));
    return a;
}
__device__ __forceinline__ void ldsm_x4(uint32_t* r, uint32_t addr) {
    asm volatile("ldmatrix.sync.aligned.m8n8.x4.shared.b16 {%0,%1,%2,%3}, [%4];"
        : "=r"(r[0]), "=r"(r[1]), "=r"(r[2]), "=r"(r[3]) : "r"(addr));
}
__device__ __forceinline__ void ldsm_x4t(uint32_t* r, uint32_t addr) {
    asm volatile("ldmatrix.sync.aligned.m8n8.x4.trans.shared.b16 {%0,%1,%2,%3}, [%4];"
        : "=r"(r[0]), "=r"(r[1]), "=r"(r[2]), "=r"(r[3]) : "r"(addr));
}
__device__ __forceinline__ void mma_bf16(float* c, const uint32_t* a, const uint32_t* b) {
    asm volatile("mma.sync.aligned.m16n8k16.row.col.f32.bf16.bf16.f32 "
        "{%0,%1,%2,%3}, {%4,%5,%6,%7}, {%8,%9}, {%0,%1,%2,%3};"
        : "+f"(c[0]), "+f"(c[1]), "+f"(c[2]), "+f"(c[3])
        : "r"(a[0]), "r"(a[1]), "r"(a[2]), "r"(a[3]), "r"(b[0]), "r"(b[1]));
}
__device__ __forceinline__ void cp16(uint32_t dst, const void* src) {
    asm volatile("cp.async.cg.shared.global [%0], [%1], 16;" :: "r"(dst), "l"(src));
}
#define CP_COMMIT() asm volatile("cp.async.commit_group;" ::: "memory")
#define CP_WAIT1()  asm volatile("cp.async.wait_group 1;" ::: "memory")

__device__ __forceinline__ void store2(float* p, float x, float y) {
    *(float2*)p = make_float2(x, y);
}
__device__ __forceinline__ void store2(__nv_bfloat16* p, float x, float y) {
    *(__nv_bfloat162*)p = __floats2bfloat162_rn(x, y);
}
__device__ __forceinline__ uint32_t pack_bf2(float x, float y) {
    __nv_bfloat162 h = __floats2bfloat162_rn(x, y);
    return *reinterpret_cast<uint32_t*>(&h);
}

// ---------------------------------------------------------------------------
// Scratch
// ---------------------------------------------------------------------------
__device__ float g_stats[NBAT * NGRP * 2];
__device__ __align__(16) __nv_bfloat16 g_wadjb[NBAT * 768 * 256];  // GN-folded QKV weights [b][m][k]
__device__ __align__(16) __nv_bfloat16 g_owb[256 * 256];           // o_w bf16 [o][c]
__device__ float g_badj[NBAT * 768];
__device__ __align__(16) __nv_bfloat16 g_qbf[(size_t)NBAT * CCH * HWC];  // q in bf16
__device__ __align__(16) __nv_bfloat16 g_qkv[(size_t)NBAT * 768 * HWC];  // [b][768][HW] bf16
__device__ __align__(16) __nv_bfloat16 g_attn[(size_t)NBAT * 256 * HWC]; // [b][C][HW] bf16

// ---------------------------------------------------------------------------
// K1: GroupNorm statistics + q -> bf16 conversion (fused; same pass)
// ---------------------------------------------------------------------------
__global__ __launch_bounds__(512) void gn_stats_kernel(const float* __restrict__ q,
                                                       __nv_bfloat16* __restrict__ qbf)
{
    int bg = blockIdx.x;
    const float4* base = (const float4*)(q + (size_t)bg * CPG * HWC);
    __nv_bfloat16* qb = qbf + (size_t)bg * CPG * HWC;
    float s = 0.f, s2 = 0.f;
    for (int i = threadIdx.x; i < (CPG * HWC) / 4; i += 512) {
        float4 v = base[i];
        s  += v.x + v.y + v.z + v.w;
        s2 += v.x*v.x + v.y*v.y + v.z*v.z + v.w*v.w;
        uint2 u;
        u.x = pack_bf2(v.x, v.y);
        u.y = pack_bf2(v.z, v.w);
        *(uint2*)(qb + (size_t)i * 4) = u;
    }
    __shared__ float rs[512], rs2[512];
    rs[threadIdx.x] = s; rs2[threadIdx.x] = s2;
    __syncthreads();
    for (int off = 256; off > 0; off >>= 1) {
        if (threadIdx.x < off) {
            rs [threadIdx.x] += rs [threadIdx.x + off];
            rs2[threadIdx.x] += rs2[threadIdx.x + off];
        }
        __syncthreads();
    }
    if (threadIdx.x == 0) {
        const float invN = 1.f / (float)(CPG * HWC);
        float mean = rs[0] * invN;
        float var  = rs2[0] * invN - mean * mean;
        g_stats[bg * 2 + 0] = mean;
        g_stats[bg * 2 + 1] = rsqrtf(var + 1e-6f);
    }
}

// ---------------------------------------------------------------------------
// K2: fold GroupNorm into QKV weights -> bf16 [b][m][k]; 32^-0.5 folded into k.
// ---------------------------------------------------------------------------
__global__ __launch_bounds__(256) void prep_weights_kernel(
    const float* __restrict__ q_w, const float* __restrict__ q_b,
    const float* __restrict__ k_w, const float* __restrict__ k_b,
    const float* __restrict__ v_w, const float* __restrict__ v_b,
    const float* __restrict__ gn_w, const float* __restrict__ gn_b)
{
    int m = blockIdx.x;
    int b = blockIdx.y;
    int t = m >> 8, o = m & 255;
    const float* W; const float* Bv;
    if      (t == 0) { W = q_w; Bv = q_b; }
    else if (t == 1) { W = k_w; Bv = k_b; }
    else             { W = v_w; Bv = v_b; }
    const float KS = (t == 1) ? 0.17677669529663687f : 1.0f;

    int c = threadIdx.x;
    int g = c >> 3;
    float mean = g_stats[(b * NGRP + g) * 2 + 0];
    float rstd = g_stats[(b * NGRP + g) * 2 + 1];
    float sc = rstd * gn_w[c];
    float sh = gn_b[c] - mean * sc;
    float wv = W[o * 256 + c];

    g_wadjb[((size_t)b * 768 + m) * 256 + c] = __float2bfloat16(wv * sc * KS);

    __shared__ float red[256];
    red[c] = wv * sh;
    __syncthreads();
    for (int off = 128; off > 0; off >>= 1) {
        if (c < off) red[c] += red[c + off];
        __syncthreads();
    }
    if (c == 0) g_badj[(size_t)b * 768 + m] = (Bv[o] + red[0]) * KS;
}

__global__ __launch_bounds__(256) void prep_ow_kernel(const float* __restrict__ ow)
{
    int o = blockIdx.x, c = threadIdx.x;
    g_owb[o * 256 + c] = __float2bfloat16(ow[o * 256 + c]);
}

// ---------------------------------------------------------------------------
// K3/K5: bf16 mma.sync GEMM, 2 CTAs/SM, CTA tile 128m x 128n.
// out[b][m][n] = sum_k A[m][k]*X[b][k][n] + bias.
//   Xs: [k=256][n=128] bf16, 256B rows, 16B-chunk XOR swizzle (ch ^ (k&7)). 64KB.
//   As: quarter-K tiles [m=128][k=64] bf16, 128B rows, ch ^ (m&7).
//       3 buffers x 16KB, cp.async prefetch 2 quarters ahead (wait_group 1).
// 8 warps (4m x 2n), warp tile 32m x 64n. Total smem 112KB -> 2 CTAs/SM.
// ---------------------------------------------------------------------------
#define SM_X    0
#define SM_A    65536
#define SM_TOT  114688

// stage X tile (bf16 source, cp.async; joins the current commit group)
__device__ __forceinline__ void stage_x(uint32_t sb, const __nv_bfloat16* Xb, int tid)
{
#pragma unroll 4
    for (int i = tid; i < 4096; i += 256) {
        int k = i >> 4, g = i & 15;
        cp16(sb + SM_X + k * 256 + ((g ^ (k & 7)) << 4),
             Xb + (size_t)k * HWC + g * 8);
    }
}
// stage A quarter tile: 128m x 64k bf16 (Asrc points at [m0][k_quarter0])
__device__ __forceinline__ void stage_aq(uint32_t sb, const __nv_bfloat16* Asrc,
                                         uint32_t buf, int tid)
{
#pragma unroll
    for (int i = tid; i < 1024; i += 256) {
        int m = i >> 3, ch = i & 7;
        cp16(sb + SM_A + buf * 16384 + m * 128 + ((ch ^ (m & 7)) << 4),
             Asrc + (size_t)m * 256 + ch * 8);
    }
}

template <int MT, bool RES, typename TOUT>
__global__ __launch_bounds__(256, 2) void gemm_mma_kernel(
    const __nv_bfloat16* __restrict__ Abf, long long Abs,
    const float* __restrict__ bias, int biasBs,
    const __nv_bfloat16* __restrict__ X, long long Xbs,
    TOUT* __restrict__ out, long long Obs,
    const float* __restrict__ res, float scale)
{
    extern __shared__ char smem[];
    const uint32_t sb = smem_u32(smem);
    const int tid = threadIdx.x, wid = tid >> 5, lane = tid & 31;
    const int b = blockIdx.y;
    const int n0 = blockIdx.x * 128;

    const __nv_bfloat16* Ab = Abf + (size_t)b * Abs;

    // ---- prologue: group0 = {X tile, A q0}; group1 = {A q1} ----
    stage_x(sb, X + (size_t)b * Xbs + n0, tid);
    stage_aq(sb, Ab, 0, tid);
    CP_COMMIT();
    stage_aq(sb, Ab + 64, 1, tid);          // quarter 1 = [m0][k=64]
    CP_COMMIT();

    // ---- per-lane ldmatrix invariants ----
    const int wm = (wid & 3) * 32;               // warp m offset
    const int wn = (wid >> 2) * 64;              // warp n offset
    const int arow = wm + (lane & 15);
    const int asel = lane >> 4;
    const int ar7  = arow & 7;
    const int gg = lane >> 3, ll = lane & 7;
    const int kbl = (gg & 1) * 8 + ll;           // k row offset within 16-step
    const int br7 = kbl & 7;
    uint32_t bBase[4];
#pragma unroll
    for (int j = 0; j < 4; j++) {
        int cn = (wn >> 3) + j * 2 + (gg >> 1);
        bBase[j] = sb + SM_X + (uint32_t)kbl * 256 + (uint32_t)((cn ^ br7) << 4);
    }
    const int er = lane >> 2, ec = (lane & 3) * 2;

    int cur = 0;                                  // qi % 3
    for (int mt = 0; mt < MT; mt++) {
        float c[2][8][4];
#pragma unroll
        for (int mi = 0; mi < 2; mi++)
#pragma unroll
            for (int ni = 0; ni < 8; ni++)
#pragma unroll
                for (int t = 0; t < 4; t++) c[mi][ni][t] = 0.f;

#pragma unroll
        for (int q = 0; q < 4; q++) {
            const int qi = mt * 4 + q;
            CP_WAIT1();                           // group qi complete (2-deep pipe)
            __syncthreads();                      // visibility + buffer-reuse guard
            const int nqi = qi + 2;
            if (nqi < MT * 4) {
                const int nbuf = (cur == 0) ? 2 : cur - 1;   // (qi+2) % 3
                stage_aq(sb, Ab + (size_t)(nqi >> 2) * 32768 + (nqi & 3) * 64,
                         (uint32_t)nbuf, tid);
            }
            CP_COMMIT();
            const uint32_t abuf = sb + SM_A + (uint32_t)cur * 16384;

#pragma unroll
            for (int ksl = 0; ksl < 4; ksl++) {
                uint32_t a0[4], a1[4];
                const uint32_t aoff = (uint32_t)(((ksl * 2 + asel) ^ ar7) << 4);
                ldsm_x4(a0, abuf + (uint32_t)arow * 128 + aoff);
                ldsm_x4(a1, abuf + (uint32_t)(arow + 16) * 128 + aoff);
                const uint32_t xoff = (uint32_t)(q * 16384 + ksl * 4096);
                uint32_t bf[8][2];
#pragma unroll
                for (int j = 0; j < 4; j++) {
                    uint32_t r[4];
                    ldsm_x4t(r, bBase[j] + xoff);
                    bf[2 * j][0] = r[0];     bf[2 * j][1] = r[1];
                    bf[2 * j + 1][0] = r[2]; bf[2 * j + 1][1] = r[3];
                }
#pragma unroll
                for (int ni = 0; ni < 8; ni++) {
                    mma_bf16(c[0][ni], a0, bf[ni]);
                    mma_bf16(c[1][ni], a1, bf[ni]);
                }
            }
            cur = (cur == 2) ? 0 : cur + 1;
        }

        // ---- epilogue ----
#pragma unroll
        for (int mi = 0; mi < 2; mi++) {
            const int m0g = mt * 128 + wm + mi * 16 + er;
            const float bv0 = bias[(size_t)b * biasBs + m0g];
            const float bv1 = bias[(size_t)b * biasBs + m0g + 8];
            TOUT* o0 = out + (size_t)b * Obs + (size_t)m0g * HWC + n0 + wn + ec;
            TOUT* o1 = o0 + 8 * HWC;
            const float* r0 = RES ? (res + (size_t)b * Obs + (size_t)m0g * HWC + n0 + wn + ec)
                                  : nullptr;
            const float* r1 = RES ? (r0 + 8 * HWC) : nullptr;
#pragma unroll
            for (int ni = 0; ni < 8; ni++) {
                float x0 = c[mi][ni][0] + bv0, y0 = c[mi][ni][1] + bv0;
                float x1 = c[mi][ni][2] + bv1, y1 = c[mi][ni][3] + bv1;
                if (RES) {
                    float2 q0 = *(const float2*)(r0 + ni * 8);
                    float2 q1 = *(const float2*)(r1 + ni * 8);
                    x0 = (x0 + q0.x) * scale; y0 = (y0 + q0.y) * scale;
                    x1 = (x1 + q1.x) * scale; y1 = (y1 + q1.y) * scale;
                }
                store2(o0 + ni * 8, x0, y0);
                store2(o1 + ni * 8, x1, y1);
            }
        }
    }
}

// ---------------------------------------------------------------------------
// K4: windowed MHA with mma.sync bf16 (unchanged — validated).
// ---------------------------------------------------------------------------
__global__ __launch_bounds__(128) void attn_mma_kernel(
    const __nv_bfloat16* __restrict__ qkv, __nv_bfloat16* __restrict__ attn)
{
    __shared__ __align__(16) char smem[24576];
    const int tid = threadIdx.x, wid = tid >> 5, lane = tid & 31;
    const int win = blockIdx.x, hp = blockIdx.y, b = blockIdx.z;
    const int wy = win >> 5, wx = win & 31;
    const int h0 = wy * 8, w0 = wx * 8;

    {
        const size_t gbase = (size_t)b * 768 * HWC;
#pragma unroll
        for (int idx = tid; idx < 1536; idx += 128) {
            int tr = idx & 7, d = (idx >> 3) & 31, whl = (idx >> 8) & 1, t = idx >> 9;
            int ch = t * 256 + (hp * 2 + whl) * 32 + d;
            uint4 v = *(const uint4*)(qkv + gbase + (size_t)ch * HWC
                                      + (size_t)(h0 + tr) * 256 + w0);
            *(uint4*)(smem + whl * 12288 + t * 4096 + d * 128 + ((tr ^ (d & 7)) << 4)) = v;
        }
    }
    __syncthreads();

    const uint32_t sb = smem_u32(smem);
    const int whl = wid >> 1, wpair = wid & 1;
    const uint32_t Qs = sb + whl * 12288;
    const uint32_t Ks = Qs + 4096;
    const uint32_t Vs = Qs + 8192;
    const int mbase = wpair * 32;

    const int rlo = lane & 7, rsel = lane >> 4, csel = (lane >> 3) & 1;

    uint32_t qa[2][2][4];
#pragma unroll
    for (int mi = 0; mi < 2; mi++)
#pragma unroll
        for (int ks = 0; ks < 2; ks++) {
            int rd = ks * 16 + rsel * 8 + rlo;
            int chunk = (mbase >> 3) + mi * 2 + csel;
            ldsm_x4t(qa[mi][ks], Qs + rd * 128 + ((chunk ^ (rd & 7)) << 4));
        }

    float c[2][8][4];
#pragma unroll
    for (int mi = 0; mi < 2; mi++)
#pragma unroll
        for (int ni = 0; ni < 8; ni++)
#pragma unroll
            for (int t = 0; t < 4; t++) c[mi][ni][t] = 0.f;

#pragma unroll
    for (int ks = 0; ks < 2; ks++) {
        int rd = ks * 16 + rsel * 8 + rlo;
#pragma unroll
        for (int ng = 0; ng < 4; ng++) {
            int chunk = ng * 2 + csel;
            uint32_t r[4];
            ldsm_x4t(r, Ks + rd * 128 + ((chunk ^ (rd & 7)) << 4));
            uint32_t b0[2] = {r[0], r[2]}, b1[2] = {r[1], r[3]};
            mma_bf16(c[0][ng * 2],     qa[0][ks], b0);
            mma_bf16(c[0][ng * 2 + 1], qa[0][ks], b1);
            mma_bf16(c[1][ng * 2],     qa[1][ks], b0);
            mma_bf16(c[1][ng * 2 + 1], qa[1][ks], b1);
        }
    }

    float rs[2][2] = {{0.f, 0.f}, {0.f, 0.f}};
    uint32_t pa[2][4][4];
#pragma unroll
    for (int mi = 0; mi < 2; mi++)
#pragma unroll
        for (int ni = 0; ni < 8; ni++) {
            float e0 = __expf(c[mi][ni][0]);
            float e1 = __expf(c[mi][ni][1]);
            float e2 = __expf(c[mi][ni][2]);
            float e3 = __expf(c[mi][ni][3]);
            rs[mi][0] += e0 + e1;
            rs[mi][1] += e2 + e3;
            int ks = ni >> 1, half = ni & 1;
            pa[mi][ks][half * 2]     = pack_bf2(e0, e1);
            pa[mi][ks][half * 2 + 1] = pack_bf2(e2, e3);
        }
#pragma unroll
    for (int mi = 0; mi < 2; mi++)
#pragma unroll
        for (int j = 0; j < 2; j++) {
            rs[mi][j] += __shfl_xor_sync(0xffffffff, rs[mi][j], 1);
            rs[mi][j] += __shfl_xor_sync(0xffffffff, rs[mi][j], 2);
        }

    float o[2][4][4];
#pragma unroll
    for (int mi = 0; mi < 2; mi++)
#pragma unroll
        for (int nj = 0; nj < 4; nj++)
#pragma unroll
            for (int t = 0; t < 4; t++) o[mi][nj][t] = 0.f;

#pragma unroll
    for (int ks = 0; ks < 4; ks++) {
#pragma unroll
        for (int njg = 0; njg < 2; njg++) {
            int rd = njg * 16 + rsel * 8 + rlo;
            int chunk = ks * 2 + csel;
            uint32_t r[4];
            ldsm_x4(r, Vs + rd * 128 + ((chunk ^ (rd & 7)) << 4));
            uint32_t b0[2] = {r[0], r[1]}, b1[2] = {r[2], r[3]};
            mma_bf16(o[0][njg * 2],     pa[0][ks], b0);
            mma_bf16(o[0][njg * 2 + 1], pa[0][ks], b1);
            mma_bf16(o[1][njg * 2],     pa[1][ks], b0);
            mma_bf16(o[1][njg * 2 + 1], pa[1][ks], b1);
        }
    }

    const int head = hp * 2 + whl;
    const size_t abase = ((size_t)b * 256 + head * 32) * HWC;
#pragma unroll
    for (int mi = 0; mi < 2; mi++) {
        const float inv0 = 1.f / rs[mi][0];
        const float inv1 = 1.f / rs[mi][1];
        const int t0 = mbase + mi * 16 + (lane >> 2);
        const size_t pos0 = (size_t)(h0 + (t0 >> 3)) * 256 + w0 + (t0 & 7);
        const size_t pos1 = pos0 + 256;
#pragma unroll
        for (int nj = 0; nj < 4; nj++) {
            const int d0 = nj * 8 + (lane & 3) * 2;
            __nv_bfloat16* p = attn + abase + (size_t)d0 * HWC;
            p[pos0]       = __float2bfloat16(o[mi][nj][0] * inv0);
            p[pos0 + HWC] = __float2bfloat16(o[mi][nj][1] * inv0);
            p[pos1]       = __float2bfloat16(o[mi][nj][2] * inv1);
            p[pos1 + HWC] = __float2bfloat16(o[mi][nj][3] * inv1);
        }
    }
}

// ---------------------------------------------------------------------------
// Launch
// ---------------------------------------------------------------------------
extern "C" void kernel_launch(void* const* d_in, const int* in_sizes, int n_in,
                              void* d_out, int out_size)
{
    const float* q    = (const float*)d_in[0];
    const float* gn_w = (const float*)d_in[1];
    const float* gn_b = (const float*)d_in[2];
    const float* q_w  = (const float*)d_in[3];
    const float* q_b  = (const float*)d_in[4];
    const float* k_w  = (const float*)d_in[5];
    const float* k_b  = (const float*)d_in[6];
    const float* v_w  = (const float*)d_in[7];
    const float* v_b  = (const float*)d_in[8];
    const float* o_w  = (const float*)d_in[9];
    const float* o_b  = (const float*)d_in[10];
    float* out = (float*)d_out;

    __nv_bfloat16 *p_wadjb, *p_owb, *p_qbf, *p_qkv, *p_attn;
    float *p_badj;
    cudaGetSymbolAddress((void**)&p_wadjb, g_wadjb);
    cudaGetSymbolAddress((void**)&p_owb,   g_owb);
    cudaGetSymbolAddress((void**)&p_badj,  g_badj);
    cudaGetSymbolAddress((void**)&p_qbf,   g_qbf);
    cudaGetSymbolAddress((void**)&p_qkv,   g_qkv);
    cudaGetSymbolAddress((void**)&p_attn,  g_attn);

    cudaFuncSetAttribute((const void*)gemm_mma_kernel<6, false, __nv_bfloat16>,
                         cudaFuncAttributeMaxDynamicSharedMemorySize, SM_TOT);
    cudaFuncSetAttribute((const void*)gemm_mma_kernel<2, true, float>,
                         cudaFuncAttributeMaxDynamicSharedMemorySize, SM_TOT);

    // 1. GroupNorm stats + q -> bf16
    gn_stats_kernel<<<NBAT * NGRP, 512>>>(q, p_qbf);

    // 2. Fold GN into QKV weights (bf16); o_w -> bf16
    prep_weights_kernel<<<dim3(768, NBAT), 256>>>(q_w, q_b, k_w, k_b, v_w, v_b, gn_w, gn_b);
    prep_ow_kernel<<<256, 256>>>(o_w);

    // 3. Fused (GN + QKV projection): [768 x 256] @ [256 x 65536] -> bf16
    gemm_mma_kernel<6, false, __nv_bfloat16><<<dim3(512, NBAT), 256, SM_TOT>>>(
        p_wadjb, 768LL * 256,
        p_badj, 768,
        p_qbf, (long long)CCH * HWC,
        p_qkv, 768LL * HWC,
        nullptr, 1.0f);

    // 4. Windowed attention (tensor-core)
    attn_mma_kernel<<<dim3(1024, 4, NBAT), 128>>>(p_qkv, p_attn);

    // 5. Output projection + residual + 2^-0.5 scale
    gemm_mma_kernel<2, true, float><<<dim3(512, NBAT), 256, SM_TOT>>>(
        p_owb, 0,
        o_b, 0,
        p_attn, (long long)CCH * HWC,
        out, (long long)CCH * HWC,
        q, 0.70710678118654752f);
}

// round 14
// speedup vs baseline: 1.0584x; 1.0584x over previous
#include <cuda_runtime.h>
#include <cuda_bf16.h>
#include <cstdint>
#include <cstddef>

// Problem constants
#define HWC   65536          // H*W = 256*256
#define CCH   256            // channels
#define NBAT  4
#define NHEAD 8
#define HD    32
#define NGRP  32
#define CPG   8              // channels per group

// ===========================================================================
// Helpers
// ===========================================================================
__device__ __forceinline__ uint32_t smem_u32(const void* p) {
    uint32_t a;
    asm("{ .reg .u64 t; cvta.to.shared.u64 t, %1; cvt.u32.u64 %0, t; }"
        : "=r"(a) : "l"(p));
    return a;
}
__device__ __forceinline__ void ldsm_x4(uint32_t* r, uint32_t addr) {
    asm volatile("ldmatrix.sync.aligned.m8n8.x4.shared.b16 {%0,%1,%2,%3}, [%4];"
        : "=r"(r[0]), "=r"(r[1]), "=r"(r[2]), "=r"(r[3]) : "r"(addr));
}
__device__ __forceinline__ void ldsm_x4t(uint32_t* r, uint32_t addr) {
    asm volatile("ldmatrix.sync.aligned.m8n8.x4.trans.shared.b16 {%0,%1,%2,%3}, [%4];"
        : "=r"(r[0]), "=r"(r[1]), "=r"(r[2]), "=r"(r[3]) : "r"(addr));
}
__device__ __forceinline__ void mma_bf16(float* c, const uint32_t* a, const uint32_t* b) {
    asm volatile("mma.sync.aligned.m16n8k16.row.col.f32.bf16.bf16.f32 "
        "{%0,%1,%2,%3}, {%4,%5,%6,%7}, {%8,%9}, {%0,%1,%2,%3};"
        : "+f"(c[0]), "+f"(c[1]), "+f"(c[2]), "+f"(c[3])
        : "r"(a[0]), "r"(a[1]), "r"(a[2]), "r"(a[3]), "r"(b[0]), "r"(b[1]));
}
__device__ __forceinline__ void cp16(uint32_t dst, const void* src) {
    asm volatile("cp.async.cg.shared.global [%0], [%1], 16;" :: "r"(dst), "l"(src));
}
#define CP_COMMIT() asm volatile("cp.async.commit_group;" ::: "memory")
#define CP_WAIT1()  asm volatile("cp.async.wait_group 1;" ::: "memory")

__device__ __forceinline__ void store2(float* p, float x, float y) {
    *(float2*)p = make_float2(x, y);
}
__device__ __forceinline__ void store2(__nv_bfloat16* p, float x, float y) {
    *(__nv_bfloat162*)p = __floats2bfloat162_rn(x, y);
}
__device__ __forceinline__ uint32_t pack_bf2(float x, float y) {
    __nv_bfloat162 h = __floats2bfloat162_rn(x, y);
    return *reinterpret_cast<uint32_t*>(&h);
}

// ---------------------------------------------------------------------------
// Scratch
// ---------------------------------------------------------------------------
__device__ float g_psum[NBAT * NGRP * 4 * 2];                      // partial sums [bg][slice][2]
__device__ __align__(16) __nv_bfloat16 g_wadjb[NBAT * 768 * 256];  // GN-folded QKV weights [b][m][k]
__device__ __align__(16) __nv_bfloat16 g_owb[256 * 256];           // o_w bf16 [o][c]
__device__ float g_badj[NBAT * 768];
__device__ __align__(16) __nv_bfloat16 g_qbf[(size_t)NBAT * CCH * HWC];  // q in bf16
__device__ __align__(16) __nv_bfloat16 g_qkv[(size_t)NBAT * 768 * HWC];  // [b][768][HW] bf16
__device__ __align__(16) __nv_bfloat16 g_attn[(size_t)NBAT * 256 * HWC]; // [b][C][HW] bf16

// ---------------------------------------------------------------------------
// K1: GroupNorm partial sums (4 slices per group) + q -> bf16 conversion.
// 512 blocks x 256 threads: >3 blocks/SM, latency well covered.
// ---------------------------------------------------------------------------
__global__ __launch_bounds__(256) void gn_part_kernel(const float* __restrict__ q,
                                                      __nv_bfloat16* __restrict__ qbf)
{
    const int bx = blockIdx.x;                 // 0..511
    const int bg = bx >> 2, slice = bx & 3;
    const size_t off4 = (size_t)bg * (CPG * HWC / 4) + (size_t)slice * (CPG * HWC / 16);
    const float4* base = (const float4*)q + off4;
    __nv_bfloat16* qb = qbf + off4 * 4;
    float s = 0.f, s2 = 0.f;
#pragma unroll 4
    for (int i = threadIdx.x; i < CPG * HWC / 16; i += 256) {
        float4 v = base[i];
        s  += v.x + v.y + v.z + v.w;
        s2 += v.x*v.x + v.y*v.y + v.z*v.z + v.w*v.w;
        uint2 u;
        u.x = pack_bf2(v.x, v.y);
        u.y = pack_bf2(v.z, v.w);
        *(uint2*)(qb + (size_t)i * 4) = u;
    }
    __shared__ float rs[256], rs2[256];
    rs[threadIdx.x] = s; rs2[threadIdx.x] = s2;
    __syncthreads();
    for (int off = 128; off > 0; off >>= 1) {
        if (threadIdx.x < off) {
            rs [threadIdx.x] += rs [threadIdx.x + off];
            rs2[threadIdx.x] += rs2[threadIdx.x + off];
        }
        __syncthreads();
    }
    if (threadIdx.x == 0) {
        g_psum[bx * 2 + 0] = rs[0];
        g_psum[bx * 2 + 1] = rs2[0];
    }
}

// ---------------------------------------------------------------------------
// K2: finalize stats + fold GroupNorm into QKV weights -> bf16 [b][m][k].
// 32^-0.5 folded into k projection.
// ---------------------------------------------------------------------------
__global__ __launch_bounds__(256) void prep_weights_kernel(
    const float* __restrict__ q_w, const float* __restrict__ q_b,
    const float* __restrict__ k_w, const float* __restrict__ k_b,
    const float* __restrict__ v_w, const float* __restrict__ v_b,
    const float* __restrict__ gn_w, const float* __restrict__ gn_b)
{
    int m = blockIdx.x;
    int b = blockIdx.y;
    int t = m >> 8, o = m & 255;
    const float* W; const float* Bv;
    if      (t == 0) { W = q_w; Bv = q_b; }
    else if (t == 1) { W = k_w; Bv = k_b; }
    else             { W = v_w; Bv = v_b; }
    const float KS = (t == 1) ? 0.17677669529663687f : 1.0f;

    int c = threadIdx.x;
    int g = c >> 3;
    const int bg = b * NGRP + g;
    float s  = g_psum[bg * 8 + 0] + g_psum[bg * 8 + 2] + g_psum[bg * 8 + 4] + g_psum[bg * 8 + 6];
    float s2 = g_psum[bg * 8 + 1] + g_psum[bg * 8 + 3] + g_psum[bg * 8 + 5] + g_psum[bg * 8 + 7];
    const float invN = 1.f / (float)(CPG * HWC);
    float mean = s * invN;
    float var  = s2 * invN - mean * mean;
    float rstd = rsqrtf(var + 1e-6f);

    float sc = rstd * gn_w[c];
    float sh = gn_b[c] - mean * sc;
    float wv = W[o * 256 + c];

    g_wadjb[((size_t)b * 768 + m) * 256 + c] = __float2bfloat16(wv * sc * KS);

    __shared__ float red[256];
    red[c] = wv * sh;
    __syncthreads();
    for (int off = 128; off > 0; off >>= 1) {
        if (c < off) red[c] += red[c + off];
        __syncthreads();
    }
    if (c == 0) g_badj[(size_t)b * 768 + m] = (Bv[o] + red[0]) * KS;
}

__global__ __launch_bounds__(256) void prep_ow_kernel(const float* __restrict__ ow)
{
    int o = blockIdx.x, c = threadIdx.x;
    g_owb[o * 256 + c] = __float2bfloat16(ow[o * 256 + c]);
}

// ---------------------------------------------------------------------------
// K3/K5: bf16 mma.sync GEMM, 2 CTAs/SM, CTA tile 128m x 128n (validated R13).
//   Xs: [k=256][n=128] bf16, 256B rows, 16B-chunk XOR swizzle. 64KB.
//   As: quarter-K tiles [m=128][k=64], 3 buffers x 16KB, wait_group 1 pipe.
// ---------------------------------------------------------------------------
#define SM_X    0
#define SM_A    65536
#define SM_TOT  114688

__device__ __forceinline__ void stage_x(uint32_t sb, const __nv_bfloat16* Xb, int tid)
{
#pragma unroll 4
    for (int i = tid; i < 4096; i += 256) {
        int k = i >> 4, g = i & 15;
        cp16(sb + SM_X + k * 256 + ((g ^ (k & 7)) << 4),
             Xb + (size_t)k * HWC + g * 8);
    }
}
__device__ __forceinline__ void stage_aq(uint32_t sb, const __nv_bfloat16* Asrc,
                                         uint32_t buf, int tid)
{
#pragma unroll
    for (int i = tid; i < 1024; i += 256) {
        int m = i >> 3, ch = i & 7;
        cp16(sb + SM_A + buf * 16384 + m * 128 + ((ch ^ (m & 7)) << 4),
             Asrc + (size_t)m * 256 + ch * 8);
    }
}

template <int MT, bool RES, typename TOUT>
__global__ __launch_bounds__(256, 2) void gemm_mma_kernel(
    const __nv_bfloat16* __restrict__ Abf, long long Abs,
    const float* __restrict__ bias, int biasBs,
    const __nv_bfloat16* __restrict__ X, long long Xbs,
    TOUT* __restrict__ out, long long Obs,
    const float* __restrict__ res, float scale)
{
    extern __shared__ char smem[];
    const uint32_t sb = smem_u32(smem);
    const int tid = threadIdx.x, wid = tid >> 5, lane = tid & 31;
    const int b = blockIdx.y;
    const int n0 = blockIdx.x * 128;

    const __nv_bfloat16* Ab = Abf + (size_t)b * Abs;

    // prologue: group0 = {X tile, A q0}; group1 = {A q1}
    stage_x(sb, X + (size_t)b * Xbs + n0, tid);
    stage_aq(sb, Ab, 0, tid);
    CP_COMMIT();
    stage_aq(sb, Ab + 64, 1, tid);
    CP_COMMIT();

    const int wm = (wid & 3) * 32;
    const int wn = (wid >> 2) * 64;
    const int arow = wm + (lane & 15);
    const int asel = lane >> 4;
    const int ar7  = arow & 7;
    const int gg = lane >> 3, ll = lane & 7;
    const int kbl = (gg & 1) * 8 + ll;
    const int br7 = kbl & 7;
    uint32_t bBase[4];
#pragma unroll
    for (int j = 0; j < 4; j++) {
        int cn = (wn >> 3) + j * 2 + (gg >> 1);
        bBase[j] = sb + SM_X + (uint32_t)kbl * 256 + (uint32_t)((cn ^ br7) << 4);
    }
    const int er = lane >> 2, ec = (lane & 3) * 2;

    int cur = 0;
    for (int mt = 0; mt < MT; mt++) {
        float c[2][8][4];
#pragma unroll
        for (int mi = 0; mi < 2; mi++)
#pragma unroll
            for (int ni = 0; ni < 8; ni++)
#pragma unroll
                for (int t = 0; t < 4; t++) c[mi][ni][t] = 0.f;

#pragma unroll
        for (int q = 0; q < 4; q++) {
            const int qi = mt * 4 + q;
            CP_WAIT1();
            __syncthreads();
            const int nqi = qi + 2;
            if (nqi < MT * 4) {
                const int nbuf = (cur == 0) ? 2 : cur - 1;
                stage_aq(sb, Ab + (size_t)(nqi >> 2) * 32768 + (nqi & 3) * 64,
                         (uint32_t)nbuf, tid);
            }
            CP_COMMIT();
            const uint32_t abuf = sb + SM_A + (uint32_t)cur * 16384;

#pragma unroll
            for (int ksl = 0; ksl < 4; ksl++) {
                uint32_t a0[4], a1[4];
                const uint32_t aoff = (uint32_t)(((ksl * 2 + asel) ^ ar7) << 4);
                ldsm_x4(a0, abuf + (uint32_t)arow * 128 + aoff);
                ldsm_x4(a1, abuf + (uint32_t)(arow + 16) * 128 + aoff);
                const uint32_t xoff = (uint32_t)(q * 16384 + ksl * 4096);
                uint32_t bf[8][2];
#pragma unroll
                for (int j = 0; j < 4; j++) {
                    uint32_t r[4];
                    ldsm_x4t(r, bBase[j] + xoff);
                    bf[2 * j][0] = r[0];     bf[2 * j][1] = r[1];
                    bf[2 * j + 1][0] = r[2]; bf[2 * j + 1][1] = r[3];
                }
#pragma unroll
                for (int ni = 0; ni < 8; ni++) {
                    mma_bf16(c[0][ni], a0, bf[ni]);
                    mma_bf16(c[1][ni], a1, bf[ni]);
                }
            }
            cur = (cur == 2) ? 0 : cur + 1;
        }

#pragma unroll
        for (int mi = 0; mi < 2; mi++) {
            const int m0g = mt * 128 + wm + mi * 16 + er;
            const float bv0 = bias[(size_t)b * biasBs + m0g];
            const float bv1 = bias[(size_t)b * biasBs + m0g + 8];
            TOUT* o0 = out + (size_t)b * Obs + (size_t)m0g * HWC + n0 + wn + ec;
            TOUT* o1 = o0 + 8 * HWC;
            const float* r0 = RES ? (res + (size_t)b * Obs + (size_t)m0g * HWC + n0 + wn + ec)
                                  : nullptr;
            const float* r1 = RES ? (r0 + 8 * HWC) : nullptr;
#pragma unroll
            for (int ni = 0; ni < 8; ni++) {
                float x0 = c[mi][ni][0] + bv0, y0 = c[mi][ni][1] + bv0;
                float x1 = c[mi][ni][2] + bv1, y1 = c[mi][ni][3] + bv1;
                if (RES) {
                    float2 q0 = *(const float2*)(r0 + ni * 8);
                    float2 q1 = *(const float2*)(r1 + ni * 8);
                    x0 = (x0 + q0.x) * scale; y0 = (y0 + q0.y) * scale;
                    x1 = (x1 + q1.x) * scale; y1 = (y1 + q1.y) * scale;
                }
                store2(o0 + ni * 8, x0, y0);
                store2(o1 + ni * 8, x1, y1);
            }
        }
    }
}

// ---------------------------------------------------------------------------
// K4: windowed MHA with mma.sync bf16 — 2 adjacent windows per block.
// Block = 256 threads = 8 warps = 4 (window, head) regions (2 warps each).
// Staging: consecutive thread pairs cover the 2 windows' 16B chunks -> 32B
// contiguous global reads (full sector utilization, halves L2 sector traffic).
// Per-warp compute identical to the validated R8 kernel.
// ---------------------------------------------------------------------------
__global__ __launch_bounds__(256) void attn_mma_kernel(
    const __nv_bfloat16* __restrict__ qkv, __nv_bfloat16* __restrict__ attn)
{
    __shared__ __align__(16) char smem[49152];
    const int tid = threadIdx.x, wid = tid >> 5, lane = tid & 31;
    const int bx = blockIdx.x, hp = blockIdx.y, b = blockIdx.z;
    const int wy = bx >> 4, wxp = bx & 15;       // window-pair column
    const int h0 = wy * 8;

    // ---- stage: region r = win_local*2 + head_local, 12KB each ----
    {
        const size_t gbase = (size_t)b * 768 * HWC;
#pragma unroll
        for (int idx = tid; idx < 3072; idx += 256) {
            int win_local  = idx & 1;
            int tr         = (idx >> 1) & 7;
            int d          = (idx >> 4) & 31;
            int head_local = (idx >> 9) & 1;
            int t          = idx >> 10;
            int ch = t * 256 + (hp * 2 + head_local) * 32 + d;
            uint4 v = *(const uint4*)(qkv + gbase + (size_t)ch * HWC
                                      + (size_t)(h0 + tr) * 256
                                      + wxp * 16 + win_local * 8);
            int r = win_local * 2 + head_local;
            *(uint4*)(smem + r * 12288 + t * 4096 + d * 128 + ((tr ^ (d & 7)) << 4)) = v;
        }
    }
    __syncthreads();

    const uint32_t sb = smem_u32(smem);
    const int whl = wid >> 1, wpair = wid & 1;   // whl: region 0..3
    const uint32_t Qs = sb + whl * 12288;
    const uint32_t Ks = Qs + 4096;
    const uint32_t Vs = Qs + 8192;
    const int mbase = wpair * 32;
    const int w0 = wxp * 16 + (whl >> 1) * 8;    // this warp's window x origin

    const int rlo = lane & 7, rsel = lane >> 4, csel = (lane >> 3) & 1;

    uint32_t qa[2][2][4];
#pragma unroll
    for (int mi = 0; mi < 2; mi++)
#pragma unroll
        for (int ks = 0; ks < 2; ks++) {
            int rd = ks * 16 + rsel * 8 + rlo;
            int chunk = (mbase >> 3) + mi * 2 + csel;
            ldsm_x4t(qa[mi][ks], Qs + rd * 128 + ((chunk ^ (rd & 7)) << 4));
        }

    float c[2][8][4];
#pragma unroll
    for (int mi = 0; mi < 2; mi++)
#pragma unroll
        for (int ni = 0; ni < 8; ni++)
#pragma unroll
            for (int t = 0; t < 4; t++) c[mi][ni][t] = 0.f;

#pragma unroll
    for (int ks = 0; ks < 2; ks++) {
        int rd = ks * 16 + rsel * 8 + rlo;
#pragma unroll
        for (int ng = 0; ng < 4; ng++) {
            int chunk = ng * 2 + csel;
            uint32_t r[4];
            ldsm_x4t(r, Ks + rd * 128 + ((chunk ^ (rd & 7)) << 4));
            uint32_t b0[2] = {r[0], r[2]}, b1[2] = {r[1], r[3]};
            mma_bf16(c[0][ng * 2],     qa[0][ks], b0);
            mma_bf16(c[0][ng * 2 + 1], qa[0][ks], b1);
            mma_bf16(c[1][ng * 2],     qa[1][ks], b0);
            mma_bf16(c[1][ng * 2 + 1], qa[1][ks], b1);
        }
    }

    float rs[2][2] = {{0.f, 0.f}, {0.f, 0.f}};
    uint32_t pa[2][4][4];
#pragma unroll
    for (int mi = 0; mi < 2; mi++)
#pragma unroll
        for (int ni = 0; ni < 8; ni++) {
            float e0 = __expf(c[mi][ni][0]);
            float e1 = __expf(c[mi][ni][1]);
            float e2 = __expf(c[mi][ni][2]);
            float e3 = __expf(c[mi][ni][3]);
            rs[mi][0] += e0 + e1;
            rs[mi][1] += e2 + e3;
            int ks = ni >> 1, half = ni & 1;
            pa[mi][ks][half * 2]     = pack_bf2(e0, e1);
            pa[mi][ks][half * 2 + 1] = pack_bf2(e2, e3);
        }
#pragma unroll
    for (int mi = 0; mi < 2; mi++)
#pragma unroll
        for (int j = 0; j < 2; j++) {
            rs[mi][j] += __shfl_xor_sync(0xffffffff, rs[mi][j], 1);
            rs[mi][j] += __shfl_xor_sync(0xffffffff, rs[mi][j], 2);
        }

    float o[2][4][4];
#pragma unroll
    for (int mi = 0; mi < 2; mi++)
#pragma unroll
        for (int nj = 0; nj < 4; nj++)
#pragma unroll
            for (int t = 0; t < 4; t++) o[mi][nj][t] = 0.f;

#pragma unroll
    for (int ks = 0; ks < 4; ks++) {
#pragma unroll
        for (int njg = 0; njg < 2; njg++) {
            int rd = njg * 16 + rsel * 8 + rlo;
            int chunk = ks * 2 + csel;
            uint32_t r[4];
            ldsm_x4(r, Vs + rd * 128 + ((chunk ^ (rd & 7)) << 4));
            uint32_t b0[2] = {r[0], r[1]}, b1[2] = {r[2], r[3]};
            mma_bf16(o[0][njg * 2],     pa[0][ks], b0);
            mma_bf16(o[0][njg * 2 + 1], pa[0][ks], b1);
            mma_bf16(o[1][njg * 2],     pa[1][ks], b0);
            mma_bf16(o[1][njg * 2 + 1], pa[1][ks], b1);
        }
    }

    const int head = hp * 2 + (whl & 1);
    const size_t abase = ((size_t)b * 256 + head * 32) * HWC;
#pragma unroll
    for (int mi = 0; mi < 2; mi++) {
        const float inv0 = 1.f / rs[mi][0];
        const float inv1 = 1.f / rs[mi][1];
        const int t0 = mbase + mi * 16 + (lane >> 2);
        const size_t pos0 = (size_t)(h0 + (t0 >> 3)) * 256 + w0 + (t0 & 7);
        const size_t pos1 = pos0 + 256;
#pragma unroll
        for (int nj = 0; nj < 4; nj++) {
            const int d0 = nj * 8 + (lane & 3) * 2;
            __nv_bfloat16* p = attn + abase + (size_t)d0 * HWC;
            p[pos0]       = __float2bfloat16(o[mi][nj][0] * inv0);
            p[pos0 + HWC] = __float2bfloat16(o[mi][nj][1] * inv0);
            p[pos1]       = __float2bfloat16(o[mi][nj][2] * inv1);
            p[pos1 + HWC] = __float2bfloat16(o[mi][nj][3] * inv1);
        }
    }
}

// ---------------------------------------------------------------------------
// Launch
// ---------------------------------------------------------------------------
extern "C" void kernel_launch(void* const* d_in, const int* in_sizes, int n_in,
                              void* d_out, int out_size)
{
    const float* q    = (const float*)d_in[0];
    const float* gn_w = (const float*)d_in[1];
    const float* gn_b = (const float*)d_in[2];
    const float* q_w  = (const float*)d_in[3];
    const float* q_b  = (const float*)d_in[4];
    const float* k_w  = (const float*)d_in[5];
    const float* k_b  = (const float*)d_in[6];
    const float* v_w  = (const float*)d_in[7];
    const float* v_b  = (const float*)d_in[8];
    const float* o_w  = (const float*)d_in[9];
    const float* o_b  = (const float*)d_in[10];
    float* out = (float*)d_out;

    __nv_bfloat16 *p_wadjb, *p_owb, *p_qbf, *p_qkv, *p_attn;
    float *p_badj;
    cudaGetSymbolAddress((void**)&p_wadjb, g_wadjb);
    cudaGetSymbolAddress((void**)&p_owb,   g_owb);
    cudaGetSymbolAddress((void**)&p_badj,  g_badj);
    cudaGetSymbolAddress((void**)&p_qbf,   g_qbf);
    cudaGetSymbolAddress((void**)&p_qkv,   g_qkv);
    cudaGetSymbolAddress((void**)&p_attn,  g_attn);

    cudaFuncSetAttribute((const void*)gemm_mma_kernel<6, false, __nv_bfloat16>,
                         cudaFuncAttributeMaxDynamicSharedMemorySize, SM_TOT);
    cudaFuncSetAttribute((const void*)gemm_mma_kernel<2, true, float>,
                         cudaFuncAttributeMaxDynamicSharedMemorySize, SM_TOT);

    // 1. GroupNorm partial stats + q -> bf16 (512 blocks)
    gn_part_kernel<<<NBAT * NGRP * 4, 256>>>(q, p_qbf);

    // 2. Finalize stats + fold GN into QKV weights (bf16); o_w -> bf16
    prep_weights_kernel<<<dim3(768, NBAT), 256>>>(q_w, q_b, k_w, k_b, v_w, v_b, gn_w, gn_b);
    prep_ow_kernel<<<256, 256>>>(o_w);

    // 3. Fused (GN + QKV projection): [768 x 256] @ [256 x 65536] -> bf16
    gemm_mma_kernel<6, false, __nv_bfloat16><<<dim3(512, NBAT), 256, SM_TOT>>>(
        p_wadjb, 768LL * 256,
        p_badj, 768,
        p_qbf, (long long)CCH * HWC,
        p_qkv, 768LL * HWC,
        nullptr, 1.0f);

    // 4. Windowed attention (tensor-core, 2 windows/block)
    attn_mma_kernel<<<dim3(512, 4, NBAT), 256>>>(p_qkv, p_attn);

    // 5. Output projection + residual + 2^-0.5 scale
    gemm_mma_kernel<2, true, float><<<dim3(512, NBAT), 256, SM_TOT>>>(
        p_owb, 0,
        o_b, 0,
        p_attn, (long long)CCH * HWC,
        out, (long long)CCH * HWC,
        q, 0.70710678118654752f);
}